// round 14
// baseline (speedup 1.0000x reference)
#include <cuda_runtime.h>
#include <cuda_bf16.h>
#include <math.h>
#include <float.h>
#include <stdint.h>

// Problem constants
#define BATCH 4
#define SEQ   1024
#define HID   1024
#define NHEAD 16
#define HDIM  64
#define MTOT  (BATCH * SEQ)   // 4096 rows

// ---------------------------------------------------------------------------
// Device scratch (allocation-free per harness rules) — bf16 hi/lo pairs
// ---------------------------------------------------------------------------
__device__ __align__(256) __nv_bfloat16 g_xh[MTOT * HID];
__device__ __align__(256) __nv_bfloat16 g_xl[MTOT * HID];
__device__ __align__(256) __nv_bfloat16 g_qh[MTOT * HID];
__device__ __align__(256) __nv_bfloat16 g_ql[MTOT * HID];
__device__ __align__(256) __nv_bfloat16 g_kh[MTOT * HID];
__device__ __align__(256) __nv_bfloat16 g_kl[MTOT * HID];
__device__ __align__(256) __nv_bfloat16 g_vh[MTOT * HID];
__device__ __align__(256) __nv_bfloat16 g_vl[MTOT * HID];
__device__ __align__(256) __nv_bfloat16 g_oh[MTOT * HID];
__device__ __align__(256) __nv_bfloat16 g_ol[MTOT * HID];

// Transposed, split weights: Wt[n][k] = W[k][n]
__device__ __align__(256) __nv_bfloat16 g_wqh[HID * HID];
__device__ __align__(256) __nv_bfloat16 g_wql[HID * HID];
__device__ __align__(256) __nv_bfloat16 g_wkh[HID * HID];
__device__ __align__(256) __nv_bfloat16 g_wkl[HID * HID];
__device__ __align__(256) __nv_bfloat16 g_wvh[HID * HID];
__device__ __align__(256) __nv_bfloat16 g_wvl[HID * HID];
__device__ __align__(256) __nv_bfloat16 g_woh[HID * HID];
__device__ __align__(256) __nv_bfloat16 g_wol[HID * HID];

// ---------------------------------------------------------------------------
// Helpers (base-sm_100-safe PTX: cp.async, ldmatrix, mma.sync)
// ---------------------------------------------------------------------------
static __device__ __forceinline__ uint32_t s2u(const void* p) {
    uint32_t a;
    asm("{ .reg .u64 t; cvta.to.shared.u64 t, %1; cvt.u32.u64 %0, t; }"
        : "=r"(a) : "l"(p));
    return a;
}

static __device__ __forceinline__ void cpasync16(uint32_t dst, const void* src) {
    asm volatile("cp.async.cg.shared.global [%0], [%1], 16;"
                 :: "r"(dst), "l"(src));
}

static __device__ __forceinline__ void ldx4(uint32_t* r, uint32_t addr) {
    asm volatile("ldmatrix.sync.aligned.m8n8.x4.shared.b16 {%0,%1,%2,%3}, [%4];"
                 : "=r"(r[0]), "=r"(r[1]), "=r"(r[2]), "=r"(r[3]) : "r"(addr));
}

static __device__ __forceinline__ void ldx4t(uint32_t* r, uint32_t addr) {
    asm volatile("ldmatrix.sync.aligned.m8n8.x4.trans.shared.b16 {%0,%1,%2,%3}, [%4];"
                 : "=r"(r[0]), "=r"(r[1]), "=r"(r[2]), "=r"(r[3]) : "r"(addr));
}

#define MMA_BF16(d, a, b)                                                     \
    asm volatile(                                                             \
        "mma.sync.aligned.m16n8k16.row.col.f32.bf16.bf16.f32 "                \
        "{%0,%1,%2,%3},{%4,%5,%6,%7},{%8,%9},{%0,%1,%2,%3};"                  \
        : "+f"((d)[0]), "+f"((d)[1]), "+f"((d)[2]), "+f"((d)[3])              \
        : "r"((a)[0]), "r"((a)[1]), "r"((a)[2]), "r"((a)[3]),                 \
          "r"((b)[0]), "r"((b)[1]))

static __device__ __forceinline__ uint32_t packbf(float a, float b) {
    __nv_bfloat162 t = __floats2bfloat162_rn(a, b);
    return *(uint32_t*)&t;
}
static __device__ __forceinline__ float bflo(float v) {
    return v - __bfloat162float(__float2bfloat16(v));
}
static __device__ __forceinline__ float ex2f(float x) {
    float y;
    asm("ex2.approx.f32 %0, %1;" : "=f"(y) : "f"(x));
    return y;
}

// ---------------------------------------------------------------------------
// Split conversion: fp32 -> (hi, lo) bf16
// ---------------------------------------------------------------------------
__global__ __launch_bounds__(256)
void convert_hilo(const float4* __restrict__ in,
                  __nv_bfloat162* __restrict__ hi,
                  __nv_bfloat162* __restrict__ lo)
{
    const int i = blockIdx.x * 256 + threadIdx.x;
    float4 v = in[i];
    __nv_bfloat16 h0 = __float2bfloat16(v.x);
    __nv_bfloat16 h1 = __float2bfloat16(v.y);
    __nv_bfloat16 h2 = __float2bfloat16(v.z);
    __nv_bfloat16 h3 = __float2bfloat16(v.w);
    __nv_bfloat162 H0; H0.x = h0; H0.y = h1;
    __nv_bfloat162 H1; H1.x = h2; H1.y = h3;
    __nv_bfloat162 L0; L0.x = __float2bfloat16(v.x - __bfloat162float(h0));
    L0.y = __float2bfloat16(v.y - __bfloat162float(h1));
    __nv_bfloat162 L1; L1.x = __float2bfloat16(v.z - __bfloat162float(h2));
    L1.y = __float2bfloat16(v.w - __bfloat162float(h3));
    hi[2 * i] = H0; hi[2 * i + 1] = H1;
    lo[2 * i] = L0; lo[2 * i + 1] = L1;
}

// ---------------------------------------------------------------------------
// Fused transpose + split: 4 weights in one launch (grid.z selects)
// ---------------------------------------------------------------------------
struct TransArgs {
    const float* W[4];
    __nv_bfloat16* th[4];
    __nv_bfloat16* tl[4];
};

__global__ __launch_bounds__(256)
void transpose_hilo4(TransArgs args)
{
    const int z = blockIdx.z;
    const float* W = args.W[z];
    __nv_bfloat16* th = args.th[z];
    __nv_bfloat16* tl = args.tl[z];

    __shared__ float tile[32][33];
    const int n0 = blockIdx.x * 32, k0 = blockIdx.y * 32;
    const int tx = threadIdx.x & 31, ty = threadIdx.x >> 5;

    #pragma unroll
    for (int i = 0; i < 4; i++) {
        const int k = ty + i * 8;
        tile[k][tx] = W[(size_t)(k0 + k) * HID + n0 + tx];
    }
    __syncthreads();
    #pragma unroll
    for (int i = 0; i < 4; i++) {
        const int n = ty + i * 8;
        const float v = tile[tx][n];
        const __nv_bfloat16 h = __float2bfloat16(v);
        th[(size_t)(n0 + n) * HID + k0 + tx] = h;
        tl[(size_t)(n0 + n) * HID + k0 + tx] = __float2bfloat16(v - __bfloat162float(h));
    }
}

// ---------------------------------------------------------------------------
// mma.sync split-bf16 GEMM: C = A @ Wt^T + bias.
// WIDE-N tile — CTA 128x256, 8 warps (2M x 4N), warp tile 64x64.
// A-fragment reuse across 8 n-tiles cuts smem traffic to 85 B/MMA (was 256):
// LDS ~2.0 kcyc vs tensor ~13.3 kcyc per SM-chunk -> decisively tensor-bound.
// 1 CTA/SM (acc=128 regs), 3-stage cp.async ring, 144 KB smem.
// ---------------------------------------------------------------------------
#define KC 32
#define NCHUNK (HID / KC)            // 32
#define ATILEB (128 * 64)            // 8 KB  (A: 128 rows x 64 B)
#define BTILEB (256 * 64)            // 16 KB (B: 256 rows x 64 B)
#define STAGEB (2 * ATILEB + 2 * BTILEB)   // 48 KB: Ah, Al, Bh, Bl
#define NSTAGE 3
#define GEMM_SMEM (NSTAGE * STAGEB)  // 144 KB

struct GemmArgs {
    const __nv_bfloat16* Bh[3];
    const __nv_bfloat16* Bl[3];
    const float* bias[3];
    __nv_bfloat16* Ch[3];
    __nv_bfloat16* Cl[3];
};

template<bool BF16OUT>
__global__ __launch_bounds__(256, 1)
void gemm256_mma(const __nv_bfloat16* __restrict__ Ah, const __nv_bfloat16* __restrict__ Al,
                 GemmArgs args, float* __restrict__ Cf)
{
    extern __shared__ char smem[];
    const int z    = blockIdx.z;
    const int tid  = threadIdx.x;
    const int wid  = tid >> 5;
    const int lane = tid & 31;
    const int wm   = wid >> 2;       // 0..1  (M warp, 64 rows)
    const int wn   = wid & 3;        // 0..3  (N warp, 64 cols)
    const int brow = blockIdx.y * 128;
    const int bcol = blockIdx.x * 256;

    const __nv_bfloat16* Bh = args.Bh[z];
    const __nv_bfloat16* Bl = args.Bl[z];
    const float* bias = args.bias[z];

    const uint32_t sbase = s2u(smem);

    const char* pA[2] = { (const char*)(Ah + (size_t)brow * HID),
                          (const char*)(Al + (size_t)brow * HID) };
    const char* pB[2] = { (const char*)(Bh + (size_t)bcol * HID),
                          (const char*)(Bl + (size_t)bcol * HID) };

    const int rowl  = lane & 15;
    const int kca   = lane >> 4;
    const int nrowl = (lane & 7) + ((lane >> 4) & 1) * 8;
    const int kcb   = (lane >> 3) & 1;

    // Stage layout: [Ah 8K][Al 8K][Bh 16K][Bl 16K]
    auto load_chunk = [&](int c, int buf) {
        const uint32_t stb = sbase + buf * STAGEB;
        const size_t koff = (size_t)c * 64;
        // A tiles: 128 rows, 512 chunks each -> 2 iters of 256 threads
        #pragma unroll
        for (int t = 0; t < 2; t++) {
            const char* src = pA[t];
            const uint32_t dstb = stb + t * ATILEB;
            #pragma unroll
            for (int i = 0; i < 2; i++) {
                const int idx = tid + i * 256;       // 0..511
                const int row = idx >> 2;
                const int cc  = idx & 3;
                const int csw = cc ^ ((row >> 1) & 3);
                cpasync16(dstb + row * 64 + csw * 16,
                          src + (size_t)row * 2048 + koff + cc * 16);
            }
        }
        // B tiles: 256 rows, 1024 chunks each -> 4 iters
        #pragma unroll
        for (int t = 0; t < 2; t++) {
            const char* src = pB[t];
            const uint32_t dstb = stb + 2 * ATILEB + t * BTILEB;
            #pragma unroll
            for (int i = 0; i < 4; i++) {
                const int idx = tid + i * 256;       // 0..1023
                const int row = idx >> 2;
                const int cc  = idx & 3;
                const int csw = cc ^ ((row >> 1) & 3);
                cpasync16(dstb + row * 64 + csw * 16,
                          src + (size_t)row * 2048 + koff + cc * 16);
            }
        }
        asm volatile("cp.async.commit_group;" ::: "memory");
    };

    float acc[4][8][4];
    #pragma unroll
    for (int i = 0; i < 4; i++)
        #pragma unroll
        for (int j = 0; j < 8; j++)
            #pragma unroll
            for (int r = 0; r < 4; r++) acc[i][j][r] = 0.0f;

    load_chunk(0, 0);
    load_chunk(1, 1);
    load_chunk(2, 2);

    int buf = 0;
    for (int c = 0; c < NCHUNK; c++) {
        if (c + 2 <= NCHUNK - 1) {
            asm volatile("cp.async.wait_group 2;" ::: "memory");
        } else if (c + 1 <= NCHUNK - 1) {
            asm volatile("cp.async.wait_group 1;" ::: "memory");
        } else {
            asm volatile("cp.async.wait_group 0;" ::: "memory");
        }
        __syncthreads();

        const uint32_t Abh = sbase + buf * STAGEB;
        const uint32_t Abl = Abh + ATILEB;
        const uint32_t Bbh = Abh + 2 * ATILEB;
        const uint32_t Bbl = Bbh + BTILEB;

        #pragma unroll
        for (int ks = 0; ks < 2; ks++) {
            // B fragments: warp's 64 cols = 4 n16 tiles, hi+lo
            uint32_t bh[16], bl[16];
            #pragma unroll
            for (int nt2 = 0; nt2 < 4; nt2++) {
                const int nrow = wn * 64 + nt2 * 16 + nrowl;
                const int cb   = ks * 2 + kcb;
                const uint32_t off = nrow * 64 + ((cb ^ ((nrow >> 1) & 3)) << 4);
                ldx4(&bh[nt2 * 4], Bbh + off);
                ldx4(&bl[nt2 * 4], Bbl + off);
            }
            #pragma unroll
            for (int mt = 0; mt < 4; mt++) {
                const int rowm = wm * 64 + mt * 16 + rowl;
                const int ca   = ks * 2 + kca;
                const uint32_t off = rowm * 64 + ((ca ^ ((rowm >> 1) & 3)) << 4);
                uint32_t ah[4], al[4];
                ldx4(ah, Abh + off);
                ldx4(al, Abl + off);
                #pragma unroll
                for (int nt = 0; nt < 8; nt++) {
                    MMA_BF16(acc[mt][nt], ah, &bh[nt * 2]);
                    MMA_BF16(acc[mt][nt], ah, &bl[nt * 2]);
                    MMA_BF16(acc[mt][nt], al, &bh[nt * 2]);
                }
            }
        }
        __syncthreads();
        if (c + NSTAGE < NCHUNK) load_chunk(c + NSTAGE, buf);
        buf = (buf + 1 == NSTAGE) ? 0 : buf + 1;
    }

    const int mbase = brow + wm * 64 + (lane >> 2);
    const int nbase = bcol + wn * 64 + (lane & 3) * 2;
    __nv_bfloat16* Ch = BF16OUT ? args.Ch[z] : nullptr;
    __nv_bfloat16* Cl = BF16OUT ? args.Cl[z] : nullptr;
    #pragma unroll
    for (int mt = 0; mt < 4; mt++) {
        #pragma unroll
        for (int nt = 0; nt < 8; nt++) {
            const int m = mbase + mt * 16;
            const int n = nbase + nt * 8;
            const float b0 = bias[n], b1 = bias[n + 1];
            const float v00 = acc[mt][nt][0] + b0, v01 = acc[mt][nt][1] + b1;
            const float v10 = acc[mt][nt][2] + b0, v11 = acc[mt][nt][3] + b1;
            if (BF16OUT) {
                *(uint32_t*)(Ch + (size_t)m * HID + n)       = packbf(v00, v01);
                *(uint32_t*)(Cl + (size_t)m * HID + n)       = packbf(bflo(v00), bflo(v01));
                *(uint32_t*)(Ch + (size_t)(m + 8) * HID + n) = packbf(v10, v11);
                *(uint32_t*)(Cl + (size_t)(m + 8) * HID + n) = packbf(bflo(v10), bflo(v11));
            } else {
                float2 a; a.x = v00; a.y = v01;
                float2 c; c.x = v10; c.y = v11;
                *(float2*)(Cf + (size_t)m * HID + n)       = a;
                *(float2*)(Cf + (size_t)(m + 8) * HID + n) = c;
            }
        }
    }
}

// ---------------------------------------------------------------------------
// Flash attention with mma.sync — validated version (3-term QK^T, 3-term PV,
// max-free softmax). Both QK cross terms required (dropping them: 2.3e-3).
// CTA: 128 Q rows of one (batch, head). 8 warps, TT=64, double-buffered.
// ---------------------------------------------------------------------------
#define AT_TT 64
#define AT_NIT (SEQ / AT_TT)         // 16
#define AT_Q_BYTES 16384
#define AT_TILE 8192
#define AT_STAGE0 (2 * AT_Q_BYTES)
#define AT_SSTRIDE (4 * AT_TILE + 256)
#define ATTN_SMEM (AT_STAGE0 + 2 * AT_SSTRIDE)   // 98816; x2 = 193 KB

__global__ __launch_bounds__(256, 2)
void attn_mma(const float* __restrict__ maskp)
{
    extern __shared__ char smem[];
    const int tid  = threadIdx.x;
    const int wid  = tid >> 5;
    const int lane = tid & 31;
    const int q0   = blockIdx.x * 128;
    const int hn   = blockIdx.y;
    const int b    = blockIdx.z;

    const uint32_t sbase = s2u(smem);

    {
        const size_t rowbase = ((size_t)b * SEQ + q0) * HID + hn * HDIM;
        #pragma unroll
        for (int i = 0; i < 8; i++) {
            const int idx  = i * 256 + tid;
            const int half = idx >> 10;
            const int r    = (idx >> 3) & 127;
            const int c    = idx & 7;
            const __nv_bfloat16* src = half ? g_ql : g_qh;
            cpasync16(sbase + half * AT_Q_BYTES + r * 128 + ((c ^ (r & 7)) << 4),
                      (const char*)(src + rowbase + (size_t)r * HID) + c * 16);
        }
        asm volatile("cp.async.commit_group;" ::: "memory");
    }

    const __nv_bfloat16* tsrc[4] = { g_kh, g_kl, g_vh, g_vl };
    auto load_stage = [&](int s, int buf) {
        const uint32_t sb = sbase + AT_STAGE0 + buf * AT_SSTRIDE;
        const int t0 = s * AT_TT;
        const size_t rowbase = ((size_t)b * SEQ + t0) * HID + hn * HDIM;
        #pragma unroll
        for (int t = 0; t < 4; t++) {
            const __nv_bfloat16* src = tsrc[t];
            #pragma unroll
            for (int i = 0; i < 2; i++) {
                const int idx = tid * 2 + i;
                const int r = idx >> 3, c = idx & 7;
                cpasync16(sb + t * AT_TILE + r * 128 + ((c ^ (r & 7)) << 4),
                          (const char*)(src + rowbase + (size_t)r * HID) + c * 16);
            }
        }
        if (tid < 16)
            cpasync16(sb + 4 * AT_TILE + tid * 16,
                      (const char*)(maskp + (size_t)b * SEQ + t0) + tid * 16);
        asm volatile("cp.async.commit_group;" ::: "memory");
    };

    load_stage(0, 0);
    load_stage(1, 1);

    const int qrow = wid * 16 + (lane & 15);
    const int qcol = lane >> 4;

    float o[8][4];
    #pragma unroll
    for (int i = 0; i < 8; i++)
        #pragma unroll
        for (int j = 0; j < 4; j++) o[i][j] = 0.0f;
    float l0 = 0.0f, l1 = 0.0f;
    const float K2  = 0.125f * 1.44269504088896341f;
    const float MK2 = -4294967296.0f * 1.44269504088896341f;

    const int krow = (lane & 7) + ((lane >> 4) & 1) * 8;
    const int kch  = (lane >> 3) & 1;
    const int vrow = lane & 15;
    const int vch  = lane >> 4;

    asm volatile("cp.async.wait_group 1;" ::: "memory");
    __syncthreads();

    for (int s = 0; s < AT_NIT; s++) {
        const int buf = s & 1;
        if (s > 0) {
            asm volatile("cp.async.wait_group 1;" ::: "memory");
            __syncthreads();
        }

        const uint32_t kbh = sbase + AT_STAGE0 + buf * AT_SSTRIDE;
        const uint32_t vbh = kbh + 2 * AT_TILE;
        const float* Msm = (const float*)(smem + AT_STAGE0 + buf * AT_SSTRIDE + 4 * AT_TILE);

        float sa[8][4];
        #pragma unroll
        for (int i = 0; i < 8; i++)
            #pragma unroll
            for (int j = 0; j < 4; j++) sa[i][j] = 0.0f;

        #pragma unroll
        for (int ks = 0; ks < 4; ks++) {
            uint32_t qh[4], ql[4];
            {
                const int c = ks * 2 + qcol;
                const uint32_t off = qrow * 128 + ((c ^ (qrow & 7)) << 4);
                ldx4(qh, sbase + off);
                ldx4(ql, sbase + AT_Q_BYTES + off);
            }
            #pragma unroll
            for (int ntp = 0; ntp < 4; ntp++) {
                const int nrow = ntp * 16 + krow;
                const int cc   = ks * 2 + kch;
                const uint32_t a = kbh + nrow * 128 + ((cc ^ (nrow & 7)) << 4);
                uint32_t bh[4], bl[4];
                ldx4(bh, a);
                ldx4(bl, a + AT_TILE);
                MMA_BF16(sa[2 * ntp],     qh, bh);
                MMA_BF16(sa[2 * ntp],     qh, bl);
                MMA_BF16(sa[2 * ntp],     ql, bh);
                MMA_BF16(sa[2 * ntp + 1], qh, bh + 2);
                MMA_BF16(sa[2 * ntp + 1], qh, bl + 2);
                MMA_BF16(sa[2 * ntp + 1], ql, bh + 2);
            }
        }

        #pragma unroll
        for (int nt = 0; nt < 8; nt++) {
            const int c0 = nt * 8 + 2 * (lane & 3);
            const float mk0 = Msm[c0] * MK2;
            const float mk1 = Msm[c0 + 1] * MK2;
            sa[nt][0] = ex2f(fmaf(sa[nt][0], K2, mk0));
            sa[nt][1] = ex2f(fmaf(sa[nt][1], K2, mk1));
            sa[nt][2] = ex2f(fmaf(sa[nt][2], K2, mk0));
            sa[nt][3] = ex2f(fmaf(sa[nt][3], K2, mk1));
            l0 += sa[nt][0] + sa[nt][1];
            l1 += sa[nt][2] + sa[nt][3];
        }

        #pragma unroll
        for (int kt = 0; kt < 4; kt++) {
            uint32_t pah[4], pal[4];
            pah[0] = packbf(sa[2 * kt][0],     sa[2 * kt][1]);
            pah[1] = packbf(sa[2 * kt][2],     sa[2 * kt][3]);
            pah[2] = packbf(sa[2 * kt + 1][0], sa[2 * kt + 1][1]);
            pah[3] = packbf(sa[2 * kt + 1][2], sa[2 * kt + 1][3]);
            pal[0] = packbf(bflo(sa[2 * kt][0]),     bflo(sa[2 * kt][1]));
            pal[1] = packbf(bflo(sa[2 * kt][2]),     bflo(sa[2 * kt][3]));
            pal[2] = packbf(bflo(sa[2 * kt + 1][0]), bflo(sa[2 * kt + 1][1]));
            pal[3] = packbf(bflo(sa[2 * kt + 1][2]), bflo(sa[2 * kt + 1][3]));
            #pragma unroll
            for (int hp = 0; hp < 4; hp++) {
                const int r  = kt * 16 + vrow;
                const int cc = hp * 2 + vch;
                const uint32_t a = vbh + r * 128 + ((cc ^ (r & 7)) << 4);
                uint32_t vh[4], vl[4];
                ldx4t(vh, a);
                ldx4t(vl, a + AT_TILE);
                MMA_BF16(o[2 * hp],     pah, vh);
                MMA_BF16(o[2 * hp],     pah, vl);
                MMA_BF16(o[2 * hp],     pal, vh);
                MMA_BF16(o[2 * hp + 1], pah, vh + 2);
                MMA_BF16(o[2 * hp + 1], pah, vl + 2);
                MMA_BF16(o[2 * hp + 1], pal, vh + 2);
            }
        }

        __syncthreads();
        if (s + 2 < AT_NIT) load_stage(s + 2, buf);
    }

    l0 += __shfl_xor_sync(0xffffffffu, l0, 1);
    l0 += __shfl_xor_sync(0xffffffffu, l0, 2);
    l1 += __shfl_xor_sync(0xffffffffu, l1, 1);
    l1 += __shfl_xor_sync(0xffffffffu, l1, 2);
    const float i0 = 1.0f / l0, i1 = 1.0f / l1;

    const int r0 = q0 + wid * 16 + (lane >> 2);
    const int r1 = r0 + 8;
    const size_t b0 = ((size_t)b * SEQ + r0) * HID + hn * HDIM + 2 * (lane & 3);
    const size_t b1 = ((size_t)b * SEQ + r1) * HID + hn * HDIM + 2 * (lane & 3);
    #pragma unroll
    for (int nt = 0; nt < 8; nt++) {
        const float v00 = o[nt][0] * i0, v01 = o[nt][1] * i0;
        const float v10 = o[nt][2] * i1, v11 = o[nt][3] * i1;
        *(uint32_t*)(g_oh + b0 + nt * 8) = packbf(v00, v01);
        *(uint32_t*)(g_ol + b0 + nt * 8) = packbf(bflo(v00), bflo(v01));
        *(uint32_t*)(g_oh + b1 + nt * 8) = packbf(v10, v11);
        *(uint32_t*)(g_ol + b1 + nt * 8) = packbf(bflo(v10), bflo(v11));
    }
}

// ---------------------------------------------------------------------------
// Launch
// ---------------------------------------------------------------------------
extern "C" void kernel_launch(void* const* d_in, const int* in_sizes, int n_in,
                              void* d_out, int out_size)
{
    const float* x    = (const float*)d_in[0];
    const float* mask = (const float*)d_in[1];
    const float* Wq   = (const float*)d_in[2];
    const float* bq   = (const float*)d_in[3];
    const float* Wk   = (const float*)d_in[4];
    const float* bk   = (const float*)d_in[5];
    const float* Wv   = (const float*)d_in[6];
    const float* bv   = (const float*)d_in[7];
    const float* Wo   = (const float*)d_in[8];
    const float* bo   = (const float*)d_in[9];
    float* out = (float*)d_out;

    static int attr_set = 0;
    if (!attr_set) {
        cudaFuncSetAttribute(gemm256_mma<false>, cudaFuncAttributeMaxDynamicSharedMemorySize, GEMM_SMEM);
        cudaFuncSetAttribute(gemm256_mma<true>,  cudaFuncAttributeMaxDynamicSharedMemorySize, GEMM_SMEM);
        cudaFuncSetAttribute(attn_mma, cudaFuncAttributeMaxDynamicSharedMemorySize, ATTN_SMEM);
        attr_set = 1;
    }

    __nv_bfloat16 *xh, *xl, *qh, *ql, *kh, *kl, *vh, *vl, *oh, *ol;
    __nv_bfloat16 *wqh, *wql, *wkh, *wkl, *wvh, *wvl, *woh, *wol;
    cudaGetSymbolAddress((void**)&xh,  g_xh);
    cudaGetSymbolAddress((void**)&xl,  g_xl);
    cudaGetSymbolAddress((void**)&qh,  g_qh);
    cudaGetSymbolAddress((void**)&ql,  g_ql);
    cudaGetSymbolAddress((void**)&kh,  g_kh);
    cudaGetSymbolAddress((void**)&kl,  g_kl);
    cudaGetSymbolAddress((void**)&vh,  g_vh);
    cudaGetSymbolAddress((void**)&vl,  g_vl);
    cudaGetSymbolAddress((void**)&oh,  g_oh);
    cudaGetSymbolAddress((void**)&ol,  g_ol);
    cudaGetSymbolAddress((void**)&wqh, g_wqh);
    cudaGetSymbolAddress((void**)&wql, g_wql);
    cudaGetSymbolAddress((void**)&wkh, g_wkh);
    cudaGetSymbolAddress((void**)&wkl, g_wkl);
    cudaGetSymbolAddress((void**)&wvh, g_wvh);
    cudaGetSymbolAddress((void**)&wvl, g_wvl);
    cudaGetSymbolAddress((void**)&woh, g_woh);
    cudaGetSymbolAddress((void**)&wol, g_wol);

    // 1. Split input activations + fused weight transpose/split
    convert_hilo<<<(MTOT * HID / 4) / 256, 256>>>((const float4*)x,
                                                  (__nv_bfloat162*)xh, (__nv_bfloat162*)xl);
    TransArgs ta;
    ta.W[0] = Wq; ta.W[1] = Wk; ta.W[2] = Wv; ta.W[3] = Wo;
    ta.th[0] = wqh; ta.th[1] = wkh; ta.th[2] = wvh; ta.th[3] = woh;
    ta.tl[0] = wql; ta.tl[1] = wkl; ta.tl[2] = wvl; ta.tl[3] = wol;
    transpose_hilo4<<<dim3(HID / 32, HID / 32, 4), 256>>>(ta);

    // 2. Q/K/V projections fused in one launch (grid: 4 Ntiles x 32 Mtiles x 3)
    GemmArgs ga;
    ga.Bh[0] = wqh; ga.Bl[0] = wql; ga.bias[0] = bq; ga.Ch[0] = qh; ga.Cl[0] = ql;
    ga.Bh[1] = wkh; ga.Bl[1] = wkl; ga.bias[1] = bk; ga.Ch[1] = kh; ga.Cl[1] = kl;
    ga.Bh[2] = wvh; ga.Bl[2] = wvl; ga.bias[2] = bv; ga.Ch[2] = vh; ga.Cl[2] = vl;
    gemm256_mma<true><<<dim3(HID / 256, MTOT / 128, 3), 256, GEMM_SMEM>>>(xh, xl, ga, nullptr);

    // 3. Flash attention (tensor cores), writes bf16 hi/lo O
    attn_mma<<<dim3(SEQ / 128, NHEAD, BATCH), 256, ATTN_SMEM>>>(mask);

    // 4. Output projection (fp32 out + bias)
    GemmArgs go;
    go.Bh[0] = woh; go.Bl[0] = wol; go.bias[0] = bo; go.Ch[0] = nullptr; go.Cl[0] = nullptr;
    go.Bh[1] = go.Bh[2] = nullptr; go.Bl[1] = go.Bl[2] = nullptr;
    go.bias[1] = go.bias[2] = nullptr;
    go.Ch[1] = go.Ch[2] = nullptr; go.Cl[1] = go.Cl[2] = nullptr;
    gemm256_mma<false><<<dim3(HID / 256, MTOT / 128, 1), 256, GEMM_SMEM>>>(oh, ol, go, out);
}

// round 15
// speedup vs baseline: 1.0518x; 1.0518x over previous
#include <cuda_runtime.h>
#include <cuda_bf16.h>
#include <math.h>
#include <float.h>
#include <stdint.h>

// Problem constants
#define BATCH 4
#define SEQ   1024
#define HID   1024
#define NHEAD 16
#define HDIM  64
#define MTOT  (BATCH * SEQ)   // 4096 rows

// ---------------------------------------------------------------------------
// Device scratch (allocation-free per harness rules) — bf16 hi/lo pairs
// ---------------------------------------------------------------------------
__device__ __align__(256) __nv_bfloat16 g_xh[MTOT * HID];
__device__ __align__(256) __nv_bfloat16 g_xl[MTOT * HID];
__device__ __align__(256) __nv_bfloat16 g_qh[MTOT * HID];
__device__ __align__(256) __nv_bfloat16 g_ql[MTOT * HID];
__device__ __align__(256) __nv_bfloat16 g_kh[MTOT * HID];
__device__ __align__(256) __nv_bfloat16 g_kl[MTOT * HID];
__device__ __align__(256) __nv_bfloat16 g_vh[MTOT * HID];
__device__ __align__(256) __nv_bfloat16 g_vl[MTOT * HID];
__device__ __align__(256) __nv_bfloat16 g_oh[MTOT * HID];
__device__ __align__(256) __nv_bfloat16 g_ol[MTOT * HID];

// Transposed, split weights: Wt[n][k] = W[k][n]
__device__ __align__(256) __nv_bfloat16 g_wqh[HID * HID];
__device__ __align__(256) __nv_bfloat16 g_wql[HID * HID];
__device__ __align__(256) __nv_bfloat16 g_wkh[HID * HID];
__device__ __align__(256) __nv_bfloat16 g_wkl[HID * HID];
__device__ __align__(256) __nv_bfloat16 g_wvh[HID * HID];
__device__ __align__(256) __nv_bfloat16 g_wvl[HID * HID];
__device__ __align__(256) __nv_bfloat16 g_woh[HID * HID];
__device__ __align__(256) __nv_bfloat16 g_wol[HID * HID];

// ---------------------------------------------------------------------------
// Helpers (base-sm_100-safe PTX: cp.async, ldmatrix, mma.sync)
// ---------------------------------------------------------------------------
static __device__ __forceinline__ uint32_t s2u(const void* p) {
    uint32_t a;
    asm("{ .reg .u64 t; cvta.to.shared.u64 t, %1; cvt.u32.u64 %0, t; }"
        : "=r"(a) : "l"(p));
    return a;
}

static __device__ __forceinline__ void cpasync16(uint32_t dst, const void* src) {
    asm volatile("cp.async.cg.shared.global [%0], [%1], 16;"
                 :: "r"(dst), "l"(src));
}

static __device__ __forceinline__ void ldx4(uint32_t* r, uint32_t addr) {
    asm volatile("ldmatrix.sync.aligned.m8n8.x4.shared.b16 {%0,%1,%2,%3}, [%4];"
                 : "=r"(r[0]), "=r"(r[1]), "=r"(r[2]), "=r"(r[3]) : "r"(addr));
}

static __device__ __forceinline__ void ldx4t(uint32_t* r, uint32_t addr) {
    asm volatile("ldmatrix.sync.aligned.m8n8.x4.trans.shared.b16 {%0,%1,%2,%3}, [%4];"
                 : "=r"(r[0]), "=r"(r[1]), "=r"(r[2]), "=r"(r[3]) : "r"(addr));
}

#define MMA_BF16(d, a, b)                                                     \
    asm volatile(                                                             \
        "mma.sync.aligned.m16n8k16.row.col.f32.bf16.bf16.f32 "                \
        "{%0,%1,%2,%3},{%4,%5,%6,%7},{%8,%9},{%0,%1,%2,%3};"                  \
        : "+f"((d)[0]), "+f"((d)[1]), "+f"((d)[2]), "+f"((d)[3])              \
        : "r"((a)[0]), "r"((a)[1]), "r"((a)[2]), "r"((a)[3]),                 \
          "r"((b)[0]), "r"((b)[1]))

static __device__ __forceinline__ uint32_t packbf(float a, float b) {
    __nv_bfloat162 t = __floats2bfloat162_rn(a, b);
    return *(uint32_t*)&t;
}
static __device__ __forceinline__ float bflo(float v) {
    return v - __bfloat162float(__float2bfloat16(v));
}
static __device__ __forceinline__ float ex2f(float x) {
    float y;
    asm("ex2.approx.f32 %0, %1;" : "=f"(y) : "f"(x));
    return y;
}

// ---------------------------------------------------------------------------
// Fused prep: grid.z 0..3 = weight transpose+split, z=4 = activation split.
// One launch instead of two (removes a launch gap).
// ---------------------------------------------------------------------------
struct PrepArgs {
    const float* W[4];
    __nv_bfloat16* th[4];
    __nv_bfloat16* tl[4];
    const float4* x;
    __nv_bfloat162* xh;
    __nv_bfloat162* xl;
};

__global__ __launch_bounds__(256)
void prep_kernel(PrepArgs args)
{
    const int z = blockIdx.z;
    if (z < 4) {
        const float* W = args.W[z];
        __nv_bfloat16* th = args.th[z];
        __nv_bfloat16* tl = args.tl[z];

        __shared__ float tile[32][33];
        const int n0 = blockIdx.x * 32, k0 = blockIdx.y * 32;
        const int tx = threadIdx.x & 31, ty = threadIdx.x >> 5;

        #pragma unroll
        for (int i = 0; i < 4; i++) {
            const int k = ty + i * 8;
            tile[k][tx] = W[(size_t)(k0 + k) * HID + n0 + tx];
        }
        __syncthreads();
        #pragma unroll
        for (int i = 0; i < 4; i++) {
            const int n = ty + i * 8;
            const float v = tile[tx][n];
            const __nv_bfloat16 h = __float2bfloat16(v);
            th[(size_t)(n0 + n) * HID + k0 + tx] = h;
            tl[(size_t)(n0 + n) * HID + k0 + tx] = __float2bfloat16(v - __bfloat162float(h));
        }
    } else {
        // Activation split: 1024 blocks x 256 threads x 4 float4 = 1M float4
        const int blk = blockIdx.y * 32 + blockIdx.x;   // 0..1023
        #pragma unroll
        for (int it = 0; it < 4; it++) {
            const int i = blk * 1024 + it * 256 + threadIdx.x;
            float4 v = args.x[i];
            __nv_bfloat16 h0 = __float2bfloat16(v.x);
            __nv_bfloat16 h1 = __float2bfloat16(v.y);
            __nv_bfloat16 h2 = __float2bfloat16(v.z);
            __nv_bfloat16 h3 = __float2bfloat16(v.w);
            __nv_bfloat162 H0; H0.x = h0; H0.y = h1;
            __nv_bfloat162 H1; H1.x = h2; H1.y = h3;
            __nv_bfloat162 L0;
            L0.x = __float2bfloat16(v.x - __bfloat162float(h0));
            L0.y = __float2bfloat16(v.y - __bfloat162float(h1));
            __nv_bfloat162 L1;
            L1.x = __float2bfloat16(v.z - __bfloat162float(h2));
            L1.y = __float2bfloat16(v.w - __bfloat162float(h3));
            args.xh[2 * i] = H0; args.xh[2 * i + 1] = H1;
            args.xl[2 * i] = L0; args.xl[2 * i + 1] = L1;
        }
    }
}

// ---------------------------------------------------------------------------
// mma.sync split-bf16 GEMM: C = A @ Wt^T + bias.
// Round-10 validated shape: 256 threads, 8 warps (2M x 4N), warp tile 64x32,
// K chunk 32, 3-stage cp.async ring, 2 CTAs/SM.
// Round 15: SINGLE-SYNC mainloop — the iteration-c barrier already proves all
// warps finished compute(c-1), so the prefetch of chunk c+2 into slot
// (c+2)%3 = (c-1)%3 is issued right after it, before compute(c). Removes one
// __syncthreads per chunk and overlaps cp.async issue with MMA work.
// ---------------------------------------------------------------------------
#define KC 32
#define NCHUNK (HID / KC)            // 32
#define TILEB  (128 * 64)            // 8192 B per tile
#define STAGEB (4 * TILEB)           // 32 KB: Ah, Al, Bh, Bl
#define NSTAGE 3
#define GEMM_SMEM (NSTAGE * STAGEB)  // 96 KB

struct GemmArgs {
    const __nv_bfloat16* Bh[3];
    const __nv_bfloat16* Bl[3];
    const float* bias[3];
    __nv_bfloat16* Ch[3];
    __nv_bfloat16* Cl[3];
};

template<bool BF16OUT>
__global__ __launch_bounds__(256, 2)
void gemm128_mma(const __nv_bfloat16* __restrict__ Ah, const __nv_bfloat16* __restrict__ Al,
                 GemmArgs args, float* __restrict__ Cf)
{
    extern __shared__ char smem[];
    const int z    = blockIdx.z;
    const int tid  = threadIdx.x;
    const int wid  = tid >> 5;
    const int lane = tid & 31;
    const int wm   = wid >> 2;       // 0..1  (M warp)
    const int wn   = wid & 3;        // 0..3  (N warp)
    const int brow = blockIdx.y * 128;
    const int bcol = blockIdx.x * 128;

    const __nv_bfloat16* Bh = args.Bh[z];
    const __nv_bfloat16* Bl = args.Bl[z];
    const float* bias = args.bias[z];

    const uint32_t sbase = s2u(smem);

    const char* pA[2] = { (const char*)(Ah + (size_t)brow * HID),
                          (const char*)(Al + (size_t)brow * HID) };
    const char* pB[2] = { (const char*)(Bh + (size_t)bcol * HID),
                          (const char*)(Bl + (size_t)bcol * HID) };

    const int rowl  = lane & 15;
    const int kca   = lane >> 4;
    const int nrowl = (lane & 7) + ((lane >> 4) & 1) * 8;
    const int kcb   = (lane >> 3) & 1;

    auto load_chunk = [&](int c, int buf) {
        const uint32_t stb = sbase + buf * STAGEB;
        const size_t koff = (size_t)c * 64;
        #pragma unroll
        for (int t = 0; t < 4; t++) {
            const char* src = (t < 2) ? pA[t] : pB[t - 2];
            const uint32_t dstb = stb + t * TILEB;
            #pragma unroll
            for (int i = 0; i < 2; i++) {
                const int idx = tid + i * 256;       // 0..511
                const int row = idx >> 2;
                const int cc  = idx & 3;
                const int csw = cc ^ ((row >> 1) & 3);
                cpasync16(dstb + row * 64 + csw * 16,
                          src + (size_t)row * 2048 + koff + cc * 16);
            }
        }
        asm volatile("cp.async.commit_group;" ::: "memory");
    };

    float acc[4][4][4];
    #pragma unroll
    for (int i = 0; i < 4; i++)
        #pragma unroll
        for (int j = 0; j < 4; j++)
            #pragma unroll
            for (int r = 0; r < 4; r++) acc[i][j][r] = 0.0f;

    load_chunk(0, 0);
    load_chunk(1, 1);

    for (int c = 0; c < NCHUNK; c++) {
        // chunk c's group must be complete
        if (c < NCHUNK - 1) {
            asm volatile("cp.async.wait_group 1;" ::: "memory");
        } else {
            asm volatile("cp.async.wait_group 0;" ::: "memory");
        }
        __syncthreads();
        // prefetch chunk c+2 into slot (c+2)%3 == (c-1)%3 (freed at iter c-1;
        // the barrier above proves all warps are past compute(c-1))
        if (c + 2 < NCHUNK) load_chunk(c + 2, (c + 2) % NSTAGE);

        const int buf = c % NSTAGE;
        const uint32_t Abh = sbase + buf * STAGEB;
        const uint32_t Abl = Abh + TILEB;
        const uint32_t Bbh = Abh + 2 * TILEB;
        const uint32_t Bbl = Abh + 3 * TILEB;

        #pragma unroll
        for (int ks = 0; ks < 2; ks++) {
            uint32_t bh[8], bl[8];
            #pragma unroll
            for (int nt2 = 0; nt2 < 2; nt2++) {
                const int nrow = wn * 32 + nt2 * 16 + nrowl;
                const int cb   = ks * 2 + kcb;
                const uint32_t off = nrow * 64 + ((cb ^ ((nrow >> 1) & 3)) << 4);
                ldx4(&bh[nt2 * 4], Bbh + off);
                ldx4(&bl[nt2 * 4], Bbl + off);
            }
            #pragma unroll
            for (int mt = 0; mt < 4; mt++) {
                const int rowm = wm * 64 + mt * 16 + rowl;
                const int ca   = ks * 2 + kca;
                const uint32_t off = rowm * 64 + ((ca ^ ((rowm >> 1) & 3)) << 4);
                uint32_t ah[4], al[4];
                ldx4(ah, Abh + off);
                ldx4(al, Abl + off);
                #pragma unroll
                for (int nt = 0; nt < 4; nt++) {
                    MMA_BF16(acc[mt][nt], ah, &bh[nt * 2]);
                    MMA_BF16(acc[mt][nt], ah, &bl[nt * 2]);
                    MMA_BF16(acc[mt][nt], al, &bh[nt * 2]);
                }
            }
        }
    }

    const int mbase = brow + wm * 64 + (lane >> 2);
    const int nbase = bcol + wn * 32 + (lane & 3) * 2;
    __nv_bfloat16* Ch = BF16OUT ? args.Ch[z] : nullptr;
    __nv_bfloat16* Cl = BF16OUT ? args.Cl[z] : nullptr;
    #pragma unroll
    for (int mt = 0; mt < 4; mt++) {
        #pragma unroll
        for (int nt = 0; nt < 4; nt++) {
            const int m = mbase + mt * 16;
            const int n = nbase + nt * 8;
            const float b0 = bias[n], b1 = bias[n + 1];
            const float v00 = acc[mt][nt][0] + b0, v01 = acc[mt][nt][1] + b1;
            const float v10 = acc[mt][nt][2] + b0, v11 = acc[mt][nt][3] + b1;
            if (BF16OUT) {
                *(uint32_t*)(Ch + (size_t)m * HID + n)       = packbf(v00, v01);
                *(uint32_t*)(Cl + (size_t)m * HID + n)       = packbf(bflo(v00), bflo(v01));
                *(uint32_t*)(Ch + (size_t)(m + 8) * HID + n) = packbf(v10, v11);
                *(uint32_t*)(Cl + (size_t)(m + 8) * HID + n) = packbf(bflo(v10), bflo(v11));
            } else {
                float2 a; a.x = v00; a.y = v01;
                float2 c; c.x = v10; c.y = v11;
                *(float2*)(Cf + (size_t)m * HID + n)       = a;
                *(float2*)(Cf + (size_t)(m + 8) * HID + n) = c;
            }
        }
    }
}

// ---------------------------------------------------------------------------
// Flash attention with mma.sync — validated version (3-term QK^T, 3-term PV,
// max-free softmax). Both QK cross terms required (dropping them: 2.3e-3).
// CTA: 128 Q rows of one (batch, head). 8 warps, TT=64, double-buffered.
// ---------------------------------------------------------------------------
#define AT_TT 64
#define AT_NIT (SEQ / AT_TT)         // 16
#define AT_Q_BYTES 16384
#define AT_TILE 8192
#define AT_STAGE0 (2 * AT_Q_BYTES)
#define AT_SSTRIDE (4 * AT_TILE + 256)
#define ATTN_SMEM (AT_STAGE0 + 2 * AT_SSTRIDE)   // 98816; x2 = 193 KB

__global__ __launch_bounds__(256, 2)
void attn_mma(const float* __restrict__ maskp)
{
    extern __shared__ char smem[];
    const int tid  = threadIdx.x;
    const int wid  = tid >> 5;
    const int lane = tid & 31;
    const int q0   = blockIdx.x * 128;
    const int hn   = blockIdx.y;
    const int b    = blockIdx.z;

    const uint32_t sbase = s2u(smem);

    {
        const size_t rowbase = ((size_t)b * SEQ + q0) * HID + hn * HDIM;
        #pragma unroll
        for (int i = 0; i < 8; i++) {
            const int idx  = i * 256 + tid;
            const int half = idx >> 10;
            const int r    = (idx >> 3) & 127;
            const int c    = idx & 7;
            const __nv_bfloat16* src = half ? g_ql : g_qh;
            cpasync16(sbase + half * AT_Q_BYTES + r * 128 + ((c ^ (r & 7)) << 4),
                      (const char*)(src + rowbase + (size_t)r * HID) + c * 16);
        }
        asm volatile("cp.async.commit_group;" ::: "memory");
    }

    const __nv_bfloat16* tsrc[4] = { g_kh, g_kl, g_vh, g_vl };
    auto load_stage = [&](int s, int buf) {
        const uint32_t sb = sbase + AT_STAGE0 + buf * AT_SSTRIDE;
        const int t0 = s * AT_TT;
        const size_t rowbase = ((size_t)b * SEQ + t0) * HID + hn * HDIM;
        #pragma unroll
        for (int t = 0; t < 4; t++) {
            const __nv_bfloat16* src = tsrc[t];
            #pragma unroll
            for (int i = 0; i < 2; i++) {
                const int idx = tid * 2 + i;
                const int r = idx >> 3, c = idx & 7;
                cpasync16(sb + t * AT_TILE + r * 128 + ((c ^ (r & 7)) << 4),
                          (const char*)(src + rowbase + (size_t)r * HID) + c * 16);
            }
        }
        if (tid < 16)
            cpasync16(sb + 4 * AT_TILE + tid * 16,
                      (const char*)(maskp + (size_t)b * SEQ + t0) + tid * 16);
        asm volatile("cp.async.commit_group;" ::: "memory");
    };

    load_stage(0, 0);
    load_stage(1, 1);

    const int qrow = wid * 16 + (lane & 15);
    const int qcol = lane >> 4;

    float o[8][4];
    #pragma unroll
    for (int i = 0; i < 8; i++)
        #pragma unroll
        for (int j = 0; j < 4; j++) o[i][j] = 0.0f;
    float l0 = 0.0f, l1 = 0.0f;
    const float K2  = 0.125f * 1.44269504088896341f;
    const float MK2 = -4294967296.0f * 1.44269504088896341f;

    const int krow = (lane & 7) + ((lane >> 4) & 1) * 8;
    const int kch  = (lane >> 3) & 1;
    const int vrow = lane & 15;
    const int vch  = lane >> 4;

    asm volatile("cp.async.wait_group 1;" ::: "memory");
    __syncthreads();

    for (int s = 0; s < AT_NIT; s++) {
        const int buf = s & 1;
        if (s > 0) {
            asm volatile("cp.async.wait_group 1;" ::: "memory");
            __syncthreads();
        }

        const uint32_t kbh = sbase + AT_STAGE0 + buf * AT_SSTRIDE;
        const uint32_t vbh = kbh + 2 * AT_TILE;
        const float* Msm = (const float*)(smem + AT_STAGE0 + buf * AT_SSTRIDE + 4 * AT_TILE);

        float sa[8][4];
        #pragma unroll
        for (int i = 0; i < 8; i++)
            #pragma unroll
            for (int j = 0; j < 4; j++) sa[i][j] = 0.0f;

        #pragma unroll
        for (int ks = 0; ks < 4; ks++) {
            uint32_t qh[4], ql[4];
            {
                const int c = ks * 2 + qcol;
                const uint32_t off = qrow * 128 + ((c ^ (qrow & 7)) << 4);
                ldx4(qh, sbase + off);
                ldx4(ql, sbase + AT_Q_BYTES + off);
            }
            #pragma unroll
            for (int ntp = 0; ntp < 4; ntp++) {
                const int nrow = ntp * 16 + krow;
                const int cc   = ks * 2 + kch;
                const uint32_t a = kbh + nrow * 128 + ((cc ^ (nrow & 7)) << 4);
                uint32_t bh[4], bl[4];
                ldx4(bh, a);
                ldx4(bl, a + AT_TILE);
                MMA_BF16(sa[2 * ntp],     qh, bh);
                MMA_BF16(sa[2 * ntp],     qh, bl);
                MMA_BF16(sa[2 * ntp],     ql, bh);
                MMA_BF16(sa[2 * ntp + 1], qh, bh + 2);
                MMA_BF16(sa[2 * ntp + 1], qh, bl + 2);
                MMA_BF16(sa[2 * ntp + 1], ql, bh + 2);
            }
        }

        #pragma unroll
        for (int nt = 0; nt < 8; nt++) {
            const int c0 = nt * 8 + 2 * (lane & 3);
            const float mk0 = Msm[c0] * MK2;
            const float mk1 = Msm[c0 + 1] * MK2;
            sa[nt][0] = ex2f(fmaf(sa[nt][0], K2, mk0));
            sa[nt][1] = ex2f(fmaf(sa[nt][1], K2, mk1));
            sa[nt][2] = ex2f(fmaf(sa[nt][2], K2, mk0));
            sa[nt][3] = ex2f(fmaf(sa[nt][3], K2, mk1));
            l0 += sa[nt][0] + sa[nt][1];
            l1 += sa[nt][2] + sa[nt][3];
        }

        #pragma unroll
        for (int kt = 0; kt < 4; kt++) {
            uint32_t pah[4], pal[4];
            pah[0] = packbf(sa[2 * kt][0],     sa[2 * kt][1]);
            pah[1] = packbf(sa[2 * kt][2],     sa[2 * kt][3]);
            pah[2] = packbf(sa[2 * kt + 1][0], sa[2 * kt + 1][1]);
            pah[3] = packbf(sa[2 * kt + 1][2], sa[2 * kt + 1][3]);
            pal[0] = packbf(bflo(sa[2 * kt][0]),     bflo(sa[2 * kt][1]));
            pal[1] = packbf(bflo(sa[2 * kt][2]),     bflo(sa[2 * kt][3]));
            pal[2] = packbf(bflo(sa[2 * kt + 1][0]), bflo(sa[2 * kt + 1][1]));
            pal[3] = packbf(bflo(sa[2 * kt + 1][2]), bflo(sa[2 * kt + 1][3]));
            #pragma unroll
            for (int hp = 0; hp < 4; hp++) {
                const int r  = kt * 16 + vrow;
                const int cc = hp * 2 + vch;
                const uint32_t a = vbh + r * 128 + ((cc ^ (r & 7)) << 4);
                uint32_t vh[4], vl[4];
                ldx4t(vh, a);
                ldx4t(vl, a + AT_TILE);
                MMA_BF16(o[2 * hp],     pah, vh);
                MMA_BF16(o[2 * hp],     pah, vl);
                MMA_BF16(o[2 * hp],     pal, vh);
                MMA_BF16(o[2 * hp + 1], pah, vh + 2);
                MMA_BF16(o[2 * hp + 1], pah, vl + 2);
                MMA_BF16(o[2 * hp + 1], pal, vh + 2);
            }
        }

        __syncthreads();
        if (s + 2 < AT_NIT) load_stage(s + 2, buf);
    }

    l0 += __shfl_xor_sync(0xffffffffu, l0, 1);
    l0 += __shfl_xor_sync(0xffffffffu, l0, 2);
    l1 += __shfl_xor_sync(0xffffffffu, l1, 1);
    l1 += __shfl_xor_sync(0xffffffffu, l1, 2);
    const float i0 = 1.0f / l0, i1 = 1.0f / l1;

    const int r0 = q0 + wid * 16 + (lane >> 2);
    const int r1 = r0 + 8;
    const size_t b0 = ((size_t)b * SEQ + r0) * HID + hn * HDIM + 2 * (lane & 3);
    const size_t b1 = ((size_t)b * SEQ + r1) * HID + hn * HDIM + 2 * (lane & 3);
    #pragma unroll
    for (int nt = 0; nt < 8; nt++) {
        const float v00 = o[nt][0] * i0, v01 = o[nt][1] * i0;
        const float v10 = o[nt][2] * i1, v11 = o[nt][3] * i1;
        *(uint32_t*)(g_oh + b0 + nt * 8) = packbf(v00, v01);
        *(uint32_t*)(g_ol + b0 + nt * 8) = packbf(bflo(v00), bflo(v01));
        *(uint32_t*)(g_oh + b1 + nt * 8) = packbf(v10, v11);
        *(uint32_t*)(g_ol + b1 + nt * 8) = packbf(bflo(v10), bflo(v11));
    }
}

// ---------------------------------------------------------------------------
// Launch
// ---------------------------------------------------------------------------
extern "C" void kernel_launch(void* const* d_in, const int* in_sizes, int n_in,
                              void* d_out, int out_size)
{
    const float* x    = (const float*)d_in[0];
    const float* mask = (const float*)d_in[1];
    const float* Wq   = (const float*)d_in[2];
    const float* bq   = (const float*)d_in[3];
    const float* Wk   = (const float*)d_in[4];
    const float* bk   = (const float*)d_in[5];
    const float* Wv   = (const float*)d_in[6];
    const float* bv   = (const float*)d_in[7];
    const float* Wo   = (const float*)d_in[8];
    const float* bo   = (const float*)d_in[9];
    float* out = (float*)d_out;

    static int attr_set = 0;
    if (!attr_set) {
        cudaFuncSetAttribute(gemm128_mma<false>, cudaFuncAttributeMaxDynamicSharedMemorySize, GEMM_SMEM);
        cudaFuncSetAttribute(gemm128_mma<true>,  cudaFuncAttributeMaxDynamicSharedMemorySize, GEMM_SMEM);
        cudaFuncSetAttribute(attn_mma, cudaFuncAttributeMaxDynamicSharedMemorySize, ATTN_SMEM);
        attr_set = 1;
    }

    __nv_bfloat16 *xh, *xl, *qh, *ql, *kh, *kl, *vh, *vl, *oh, *ol;
    __nv_bfloat16 *wqh, *wql, *wkh, *wkl, *wvh, *wvl, *woh, *wol;
    cudaGetSymbolAddress((void**)&xh,  g_xh);
    cudaGetSymbolAddress((void**)&xl,  g_xl);
    cudaGetSymbolAddress((void**)&qh,  g_qh);
    cudaGetSymbolAddress((void**)&ql,  g_ql);
    cudaGetSymbolAddress((void**)&kh,  g_kh);
    cudaGetSymbolAddress((void**)&kl,  g_kl);
    cudaGetSymbolAddress((void**)&vh,  g_vh);
    cudaGetSymbolAddress((void**)&vl,  g_vl);
    cudaGetSymbolAddress((void**)&oh,  g_oh);
    cudaGetSymbolAddress((void**)&ol,  g_ol);
    cudaGetSymbolAddress((void**)&wqh, g_wqh);
    cudaGetSymbolAddress((void**)&wql, g_wql);
    cudaGetSymbolAddress((void**)&wkh, g_wkh);
    cudaGetSymbolAddress((void**)&wkl, g_wkl);
    cudaGetSymbolAddress((void**)&wvh, g_wvh);
    cudaGetSymbolAddress((void**)&wvl, g_wvl);
    cudaGetSymbolAddress((void**)&woh, g_woh);
    cudaGetSymbolAddress((void**)&wol, g_wol);

    // 1. Fused prep: weight transpose+split (z=0..3) + activation split (z=4)
    PrepArgs pa;
    pa.W[0] = Wq; pa.W[1] = Wk; pa.W[2] = Wv; pa.W[3] = Wo;
    pa.th[0] = wqh; pa.th[1] = wkh; pa.th[2] = wvh; pa.th[3] = woh;
    pa.tl[0] = wql; pa.tl[1] = wkl; pa.tl[2] = wvl; pa.tl[3] = wol;
    pa.x = (const float4*)x;
    pa.xh = (__nv_bfloat162*)xh;
    pa.xl = (__nv_bfloat162*)xl;
    prep_kernel<<<dim3(32, 32, 5), 256>>>(pa);

    // 2. Q/K/V projections fused in one launch (grid.z selects)
    GemmArgs ga;
    ga.Bh[0] = wqh; ga.Bl[0] = wql; ga.bias[0] = bq; ga.Ch[0] = qh; ga.Cl[0] = ql;
    ga.Bh[1] = wkh; ga.Bl[1] = wkl; ga.bias[1] = bk; ga.Ch[1] = kh; ga.Cl[1] = kl;
    ga.Bh[2] = wvh; ga.Bl[2] = wvl; ga.bias[2] = bv; ga.Ch[2] = vh; ga.Cl[2] = vl;
    gemm128_mma<true><<<dim3(HID / 128, MTOT / 128, 3), 256, GEMM_SMEM>>>(xh, xl, ga, nullptr);

    // 3. Flash attention (tensor cores), writes bf16 hi/lo O
    attn_mma<<<dim3(SEQ / 128, NHEAD, BATCH), 256, ATTN_SMEM>>>(mask);

    // 4. Output projection (fp32 out + bias)
    GemmArgs go;
    go.Bh[0] = woh; go.Bl[0] = wol; go.bias[0] = bo; go.Ch[0] = nullptr; go.Cl[0] = nullptr;
    go.Bh[1] = go.Bh[2] = nullptr; go.Bl[1] = go.Bl[2] = nullptr;
    go.bias[1] = go.bias[2] = nullptr;
    go.Ch[1] = go.Ch[2] = nullptr; go.Cl[1] = go.Cl[2] = nullptr;
    gemm128_mma<false><<<dim3(HID / 128, MTOT / 128, 1), 256, GEMM_SMEM>>>(oh, ol, go, out);
}